// round 1
// baseline (speedup 1.0000x reference)
#include <cuda_runtime.h>
#include <cstdint>

#define IMG_H 512
#define IMG_W 512
#define N_IMG 16
#define WORDS_PER_ROW 16              // 512 cols / 32 bits
#define WORDS_PER_IMG (IMG_H * WORDS_PER_ROW)   // 8192
#define PLANE (IMG_H * IMG_W)         // 262144

// Scratch bitmasks (device globals: allocation-free rule)
__device__ unsigned g_strong[N_IMG * WORDS_PER_IMG];
__device__ unsigned g_weak  [N_IMG * WORDS_PER_IMG];
__device__ unsigned g_edge  [N_IMG * WORDS_PER_IMG];

// ---------------------------------------------------------------------------
// K1: gray -> sobel -> mag -> NMS -> strong/weak bitmasks
// One 32x32 output tile per block (blockDim 32x32).
// ---------------------------------------------------------------------------
__global__ __launch_bounds__(1024) void canny_nms_kernel(const float* __restrict__ x) {
    const int img = blockIdx.z;
    const int tx0 = blockIdx.x * 32;
    const int ty0 = blockIdx.y * 32;

    __shared__ float gs[36][37];   // gray tile + 2 halo (edge-clamped)
    __shared__ float ms[34][35];   // mag tile + 1 halo (zero outside image)

    const int tid = threadIdx.y * 32 + threadIdx.x;
    const float* xb = x + (size_t)img * 3 * PLANE;

    // Load gray 36x36 (global coords clamped to image => 'edge' padding)
    for (int i = tid; i < 36 * 36; i += 1024) {
        int r = i / 36, c = i % 36;
        int gr = min(max(ty0 + r - 2, 0), IMG_H - 1);
        int gc = min(max(tx0 + c - 2, 0), IMG_W - 1);
        float r0 = xb[gr * IMG_W + gc];
        float g1 = xb[PLANE + gr * IMG_W + gc];
        float b2 = xb[2 * PLANE + gr * IMG_W + gc];
        // match reference op order exactly (no FMA contraction)
        float gray = __fadd_rn(__fadd_rn(__fmul_rn(0.2989f, r0),
                                         __fmul_rn(0.587f, g1)),
                               __fmul_rn(0.114f, b2));
        gray = floorf(fminf(fmaxf(gray, 0.0f), 255.0f));
        gs[r][c] = gray;
    }
    __syncthreads();

    // mag on 34x34 (tile + 1 halo); zero for pixels outside the image
    for (int i = tid; i < 34 * 34; i += 1024) {
        int r = i / 34, c = i % 34;            // gs coords: (r+1, c+1) center
        int gr = ty0 + r - 1, gc = tx0 + c - 1; // global pixel coords
        float m = 0.0f;
        if (gr >= 0 && gr < IMG_H && gc >= 0 && gc < IMG_W) {
            float a00 = gs[r][c],     a01 = gs[r][c + 1],     a02 = gs[r][c + 2];
            float a10 = gs[r + 1][c],                         a12 = gs[r + 1][c + 2];
            float a20 = gs[r + 2][c], a21 = gs[r + 2][c + 1], a22 = gs[r + 2][c + 2];
            float gx = a02 + 2.0f * a12 + a22 - a00 - 2.0f * a10 - a20;
            float gy = a20 + 2.0f * a21 + a22 - a00 - 2.0f * a01 - a02;
            m = fabsf(gx) + fabsf(gy);
        }
        ms[r][c] = m;
    }
    __syncthreads();

    // NMS at the 32x32 center; neighbor mags zero-padded outside image
    const int r = threadIdx.y, c = threadIdx.x;
    float a00 = gs[r + 1][c + 1], a01 = gs[r + 1][c + 2], a02 = gs[r + 1][c + 3];
    float a10 = gs[r + 2][c + 1],                         a12 = gs[r + 2][c + 3];
    float a20 = gs[r + 3][c + 1], a21 = gs[r + 3][c + 2], a22 = gs[r + 3][c + 3];
    float gx = a02 + 2.0f * a12 + a22 - a00 - 2.0f * a10 - a20;
    float gy = a20 + 2.0f * a21 + a22 - a00 - 2.0f * a01 - a02;
    float ax = fabsf(gx), ay = fabsf(gy);
    float mag = ax + ay;

    float e_  = ms[r + 1][c + 2], w_  = ms[r + 1][c];
    float n_  = ms[r][c + 1],     s_  = ms[r + 2][c + 1];
    float nw_ = ms[r][c],         se_ = ms[r + 2][c + 2];
    float ne_ = ms[r][c + 2],     sw_ = ms[r + 2][c];

    bool horiz = ay <= 0.4142135623730951f * ax;
    bool vert  = ay >  2.414213562373095f  * ax;
    bool ssign = gx * gy >= 0.0f;
    float n1 = horiz ? e_ : (vert ? n_ : (ssign ? nw_ : ne_));
    float n2 = horiz ? w_ : (vert ? s_ : (ssign ? se_ : sw_));
    bool keep = (mag > n1) && (mag >= n2);
    float nms = keep ? mag : 0.0f;

    unsigned strong = __ballot_sync(0xffffffffu, nms > 150.0f);
    unsigned weak   = __ballot_sync(0xffffffffu, nms > 50.0f);
    if (threadIdx.x == 0) {
        int row = ty0 + r;
        int idx = (img * IMG_H + row) * WORDS_PER_ROW + blockIdx.x;
        g_strong[idx] = strong;
        g_weak[idx]   = weak;
    }
}

// ---------------------------------------------------------------------------
// K2: hysteresis flood fill. One block per image; cur bitset in smem.
// In-place monotone OR updates; __syncthreads_or convergence => exact closure.
// ---------------------------------------------------------------------------
__global__ __launch_bounds__(1024) void hysteresis_kernel() {
    const int img = blockIdx.x;
    __shared__ unsigned cur[WORDS_PER_IMG];   // 32 KB
    const unsigned* wp = g_weak + img * WORDS_PER_IMG;
    const unsigned* sp = g_strong + img * WORDS_PER_IMG;
    const int tid = threadIdx.x;

    for (int i = tid; i < WORDS_PER_IMG; i += 1024) cur[i] = sp[i];
    __syncthreads();

    for (;;) {
        int changed = 0;
        for (int i = tid; i < WORDS_PER_IMG; i += 1024) {
            unsigned c = cur[i];
            unsigned t = __ldg(wp + i) & ~c;   // candidate bits still off
            if (t) {
                int r = i >> 4, w = i & 15;
                unsigned dil = 0;
#pragma unroll
                for (int dr = -1; dr <= 1; dr++) {
                    int rr = r + dr;
                    if (rr < 0 || rr >= IMG_H) continue;
                    int base = (rr << 4) + w;
                    unsigned m = cur[base];
                    unsigned l = (w > 0)  ? cur[base - 1] : 0u;
                    unsigned g = (w < 15) ? cur[base + 1] : 0u;
                    dil |= m | (m << 1) | (m >> 1) | (l >> 31) | (g << 31);
                }
                unsigned add = t & dil;
                if (add) { cur[i] = c | add; changed = 1; }
            }
        }
        if (!__syncthreads_or(changed)) break;
    }

    unsigned* ep = g_edge + img * WORDS_PER_IMG;
    for (int i = tid; i < WORDS_PER_IMG; i += 1024) ep[i] = cur[i];
}

// ---------------------------------------------------------------------------
// K3: epilogue. out[b,o,h,w] = relu(W[o,0..2]·x + W[o,3]*edge*255 + bias[o])
// One thread per 4 pixels (float4 in/out).
// ---------------------------------------------------------------------------
__global__ __launch_bounds__(256) void output_kernel(const float* __restrict__ x,
                                                     const float* __restrict__ Wm,
                                                     const float* __restrict__ bias,
                                                     float* __restrict__ out) {
    __shared__ float Ws[128];
    __shared__ float bs[32];
    const int tid = threadIdx.x;
    if (tid < 128) Ws[tid] = Wm[tid];
    if (tid < 32)  bs[tid] = bias[tid];
    __syncthreads();

    const long gt  = (long)blockIdx.x * blockDim.x + tid;  // 4 pixels per thread
    const int img  = (int)(gt >> 16);                      // 65536 threads/image
    const int pix  = ((int)gt & 65535) << 2;               // pixel idx in plane

    const float* xb = x + (size_t)img * 3 * PLANE;
    float4 x0 = *(const float4*)(xb + pix);
    float4 x1 = *(const float4*)(xb + PLANE + pix);
    float4 x2 = *(const float4*)(xb + 2 * PLANE + pix);

    unsigned ew = g_edge[img * WORDS_PER_IMG + (pix >> 5)];
    int sh = pix & 31;
    float e0 = ((ew >> (sh    )) & 1u) ? 255.0f : 0.0f;
    float e1 = ((ew >> (sh + 1)) & 1u) ? 255.0f : 0.0f;
    float e2 = ((ew >> (sh + 2)) & 1u) ? 255.0f : 0.0f;
    float e3 = ((ew >> (sh + 3)) & 1u) ? 255.0f : 0.0f;

    float* ob = out + (size_t)img * 32 * PLANE + pix;
#pragma unroll 8
    for (int o = 0; o < 32; o++) {
        float w0 = Ws[4 * o], w1 = Ws[4 * o + 1], w2 = Ws[4 * o + 2], w3 = Ws[4 * o + 3];
        float bb = bs[o];
        float4 v;
        v.x = fmaxf(fmaf(w0, x0.x, fmaf(w1, x1.x, fmaf(w2, x2.x, fmaf(w3, e0, bb)))), 0.0f);
        v.y = fmaxf(fmaf(w0, x0.y, fmaf(w1, x1.y, fmaf(w2, x2.y, fmaf(w3, e1, bb)))), 0.0f);
        v.z = fmaxf(fmaf(w0, x0.z, fmaf(w1, x1.z, fmaf(w2, x2.z, fmaf(w3, e2, bb)))), 0.0f);
        v.w = fmaxf(fmaf(w0, x0.w, fmaf(w1, x1.w, fmaf(w2, x2.w, fmaf(w3, e3, bb)))), 0.0f);
        *(float4*)(ob + (size_t)o * PLANE) = v;
    }
}

// ---------------------------------------------------------------------------
extern "C" void kernel_launch(void* const* d_in, const int* in_sizes, int n_in,
                              void* d_out, int out_size) {
    (void)in_sizes; (void)n_in; (void)out_size;
    const float* x  = (const float*)d_in[0];   // (16,3,512,512)
    const float* Wm = (const float*)d_in[1];   // (32,4)
    const float* b  = (const float*)d_in[2];   // (32,)
    float* out = (float*)d_out;                // (16,32,512,512)

    dim3 b1(32, 32), g1(IMG_W / 32, IMG_H / 32, N_IMG);
    canny_nms_kernel<<<g1, b1>>>(x);

    hysteresis_kernel<<<N_IMG, 1024>>>();

    int total_threads = N_IMG * PLANE / 4;     // 1,048,576
    output_kernel<<<total_threads / 256, 256>>>(x, Wm, b, out);
}

// round 2
// speedup vs baseline: 1.0897x; 1.0897x over previous
#include <cuda_runtime.h>
#include <cstdint>

#define IMG_H 512
#define IMG_W 512
#define N_IMG 16
#define WORDS_PER_ROW 16
#define WORDS_PER_IMG (IMG_H * WORDS_PER_ROW)   // 8192
#define PLANE (IMG_H * IMG_W)

__device__ unsigned g_strong[N_IMG * WORDS_PER_IMG];
__device__ unsigned g_weak  [N_IMG * WORDS_PER_IMG];
__device__ unsigned g_edge  [N_IMG * WORDS_PER_IMG];

// ---------------------------------------------------------------------------
// K1: gray -> sobel -> NMS -> strong/weak bitmasks.
// 32 wide x 64 tall tile per block, blockDim (32,16), 4 consecutive rows/thread.
// ---------------------------------------------------------------------------
__global__ __launch_bounds__(512, 2) void canny_nms_kernel(const float* __restrict__ x) {
    const int img = blockIdx.z;
    const int tx0 = blockIdx.x * 32;
    const int ty0 = blockIdx.y * 64;

    __shared__ float gs[68][37];   // gray tile + 2 halo (edge clamp), rows ty0-2..ty0+65
    __shared__ float ms[66][35];   // mag tile + 1 halo (zero pad),   rows ty0-1..ty0+64

    const int tx = threadIdx.x, ty = threadIdx.y;
    const float* xb = x + (size_t)img * 3 * PLANE;

    // Phase 1: gray 68x36
    for (int r = ty; r < 68; r += 16) {
        int gr = min(max(ty0 + r - 2, 0), IMG_H - 1);
        const float* rb = xb + gr * IMG_W;
        {
            int gc = min(max(tx0 + tx - 2, 0), IMG_W - 1);
            float g = __fadd_rn(__fadd_rn(__fmul_rn(0.2989f, rb[gc]),
                                          __fmul_rn(0.587f, rb[PLANE + gc])),
                                __fmul_rn(0.114f, rb[2 * PLANE + gc]));
            gs[r][tx] = floorf(fminf(fmaxf(g, 0.0f), 255.0f));
        }
        if (tx < 4) {
            int c = 32 + tx;
            int gc = min(max(tx0 + c - 2, 0), IMG_W - 1);
            float g = __fadd_rn(__fadd_rn(__fmul_rn(0.2989f, rb[gc]),
                                          __fmul_rn(0.587f, rb[PLANE + gc])),
                                __fmul_rn(0.114f, rb[2 * PLANE + gc]));
            gs[r][c] = floorf(fminf(fmaxf(g, 0.0f), 255.0f));
        }
    }
    __syncthreads();

    // Phase 2: mag 66x34 (zero outside image)
    for (int r = ty; r < 66; r += 16) {
        int gr = ty0 + r - 1;
#pragma unroll
        for (int c0 = 0; c0 < 64; c0 += 32) {
            int c = c0 + tx;
            if (c >= 34) break;
            int gc = tx0 + c - 1;
            float m = 0.0f;
            if ((unsigned)gr < (unsigned)IMG_H && (unsigned)gc < (unsigned)IMG_W) {
                float a00 = gs[r][c],     a01 = gs[r][c + 1],     a02 = gs[r][c + 2];
                float a10 = gs[r + 1][c],                         a12 = gs[r + 1][c + 2];
                float a20 = gs[r + 2][c], a21 = gs[r + 2][c + 1], a22 = gs[r + 2][c + 2];
                float gx = a02 + 2.0f * a12 + a22 - a00 - 2.0f * a10 - a20;
                float gy = a20 + 2.0f * a21 + a22 - a00 - 2.0f * a01 - a02;
                m = fabsf(gx) + fabsf(gy);
            }
            ms[r][c] = m;
        }
    }
    __syncthreads();

    // Phase 3: NMS, 4 consecutive rows per thread (y0..y0+3)
    const int y0 = ty * 4;

    float gcol[3][6];
#pragma unroll
    for (int cc = 0; cc < 3; cc++)
#pragma unroll
        for (int rr = 0; rr < 6; rr++)
            gcol[cc][rr] = gs[y0 + 1 + rr][tx + 1 + cc];

    float mag[4], ax[4], ay[4];
    bool ss[4];
#pragma unroll
    for (int k = 0; k < 4; k++) {
        float gx = (gcol[2][k] + 2.0f * gcol[2][k + 1] + gcol[2][k + 2])
                 - (gcol[0][k] + 2.0f * gcol[0][k + 1] + gcol[0][k + 2]);
        float gy = (gcol[0][k + 2] + 2.0f * gcol[1][k + 2] + gcol[2][k + 2])
                 - (gcol[0][k] + 2.0f * gcol[1][k] + gcol[2][k]);
        ax[k] = fabsf(gx);
        ay[k] = fabsf(gy);
        mag[k] = ax[k] + ay[k];
        ss[k] = (gx * gy >= 0.0f);
    }

    float m3[3][6];
#pragma unroll
    for (int cc = 0; cc < 3; cc++)
#pragma unroll
        for (int rr = 0; rr < 6; rr++)
            m3[cc][rr] = ms[y0 + rr][tx + cc];

#pragma unroll
    for (int k = 0; k < 4; k++) {
        float e_  = m3[2][k + 1], w_  = m3[0][k + 1];
        float n_  = m3[1][k],     s_  = m3[1][k + 2];
        float nw_ = m3[0][k],     se_ = m3[2][k + 2];
        float ne_ = m3[2][k],     sw_ = m3[0][k + 2];

        bool horiz = ay[k] <= 0.4142135623730951f * ax[k];
        bool vert  = ay[k] >  2.414213562373095f  * ax[k];
        float n1 = horiz ? e_ : (vert ? n_ : (ss[k] ? nw_ : ne_));
        float n2 = horiz ? w_ : (vert ? s_ : (ss[k] ? se_ : sw_));
        bool keep = (mag[k] > n1) && (mag[k] >= n2);
        float nms = keep ? mag[k] : 0.0f;

        unsigned sb = __ballot_sync(0xffffffffu, nms > 150.0f);
        unsigned wb = __ballot_sync(0xffffffffu, nms > 50.0f);
        if (tx == 0) {
            int row = ty0 + y0 + k;
            int idx = (img * IMG_H + row) * WORDS_PER_ROW + blockIdx.x;
            g_strong[idx] = sb;
            g_weak[idx]   = wb;
        }
    }
}

// ---------------------------------------------------------------------------
// K2: hysteresis. Thread owns 8-row x 32-col strip in registers.
// Gauss-Seidel down+up passes + in-word weak-run closure (carry trick).
// ---------------------------------------------------------------------------
__device__ __forceinline__ unsigned Hd(unsigned m, unsigned l, unsigned r) {
    return m | (m << 1) | (m >> 1) | (l >> 31) | (r << 31);
}
// g must satisfy g ⊆ w. Fills every run of 1s in w that contains a bit of g.
__device__ __forceinline__ unsigned close_runs(unsigned g, unsigned w) {
    unsigned up = ((w + g) ^ w) & w;
    unsigned rg = __brev(g), rw = __brev(w);
    unsigned dn = __brev(((rw + rg) ^ rw) & rw);
    return g | up | dn;
}

__global__ __launch_bounds__(1024) void hysteresis_kernel() {
    const int img = blockIdx.x;
    __shared__ unsigned cur[WORDS_PER_IMG];   // 32 KB
    const unsigned* wp = g_weak   + img * WORDS_PER_IMG;
    const unsigned* sp = g_strong + img * WORDS_PER_IMG;
    const int tid = threadIdx.x;
    const int w  = tid & 15;
    const int r0 = (tid >> 4) << 3;   // 64 row-groups of 8

    unsigned reg[8], wk[8];
#pragma unroll
    for (int i = 0; i < 8; i++) {
        int idx = (r0 + i) * 16 + w;
        reg[i] = sp[idx];
        wk[i]  = wp[idx];
        cur[idx] = reg[i];
    }
    __syncthreads();

    for (;;) {
        unsigned lw[10], rw[10];
#pragma unroll
        for (int j = 0; j < 10; j++) {
            int r = r0 - 1 + j;
            bool ok = (r >= 0 && r < IMG_H);
            lw[j] = (ok && w > 0)  ? cur[r * 16 + w - 1] : 0u;
            rw[j] = (ok && w < 15) ? cur[r * 16 + w + 1] : 0u;
        }
        unsigned ab = (r0 > 0)           ? cur[(r0 - 1) * 16 + w] : 0u;
        unsigned bl = (r0 + 8 < IMG_H)   ? cur[(r0 + 8) * 16 + w] : 0u;

        unsigned changed = 0;
#pragma unroll
        for (int i = 0; i < 8; i++) {   // down pass
            unsigned up_row = (i == 0) ? ab : reg[i - 1];
            unsigned dn_row = (i == 7) ? bl : reg[i + 1];
            unsigned dil = Hd(up_row, lw[i], rw[i])
                         | Hd(reg[i], lw[i + 1], rw[i + 1])
                         | Hd(dn_row, lw[i + 2], rw[i + 2]);
            unsigned g = reg[i] | (wk[i] & dil);
            unsigned nv = g ? close_runs(g, wk[i]) : 0u;
            changed |= nv ^ reg[i];
            reg[i] = nv;
        }
#pragma unroll
        for (int i = 7; i >= 0; i--) {  // up pass
            unsigned up_row = (i == 0) ? ab : reg[i - 1];
            unsigned dn_row = (i == 7) ? bl : reg[i + 1];
            unsigned dil = Hd(up_row, lw[i], rw[i])
                         | Hd(reg[i], lw[i + 1], rw[i + 1])
                         | Hd(dn_row, lw[i + 2], rw[i + 2]);
            unsigned g = reg[i] | (wk[i] & dil);
            unsigned nv = g ? close_runs(g, wk[i]) : 0u;
            changed |= nv ^ reg[i];
            reg[i] = nv;
        }

        __syncthreads();   // readers done before we overwrite
#pragma unroll
        for (int i = 0; i < 8; i++) cur[(r0 + i) * 16 + w] = reg[i];
        if (!__syncthreads_or(changed != 0)) break;
    }

    unsigned* ep = g_edge + img * WORDS_PER_IMG;
#pragma unroll
    for (int i = 0; i < 8; i++) ep[(r0 + i) * 16 + w] = reg[i];
}

// ---------------------------------------------------------------------------
// K3: epilogue (537 MB write-bound)
// ---------------------------------------------------------------------------
__global__ __launch_bounds__(256) void output_kernel(const float* __restrict__ x,
                                                     const float* __restrict__ Wm,
                                                     const float* __restrict__ bias,
                                                     float* __restrict__ out) {
    __shared__ float Ws[128];
    __shared__ float bs[32];
    const int tid = threadIdx.x;
    if (tid < 128) Ws[tid] = Wm[tid];
    if (tid < 32)  bs[tid] = bias[tid];
    __syncthreads();

    const long gt  = (long)blockIdx.x * blockDim.x + tid;
    const int img  = (int)(gt >> 16);
    const int pix  = ((int)gt & 65535) << 2;

    const float* xb = x + (size_t)img * 3 * PLANE;
    float4 x0 = *(const float4*)(xb + pix);
    float4 x1 = *(const float4*)(xb + PLANE + pix);
    float4 x2 = *(const float4*)(xb + 2 * PLANE + pix);

    unsigned ew = g_edge[img * WORDS_PER_IMG + (pix >> 5)];
    int sh = pix & 31;
    float e0 = ((ew >> (sh    )) & 1u) ? 255.0f : 0.0f;
    float e1 = ((ew >> (sh + 1)) & 1u) ? 255.0f : 0.0f;
    float e2 = ((ew >> (sh + 2)) & 1u) ? 255.0f : 0.0f;
    float e3 = ((ew >> (sh + 3)) & 1u) ? 255.0f : 0.0f;

    float* ob = out + (size_t)img * 32 * PLANE + pix;
#pragma unroll 8
    for (int o = 0; o < 32; o++) {
        float w0 = Ws[4 * o], w1 = Ws[4 * o + 1], w2 = Ws[4 * o + 2], w3 = Ws[4 * o + 3];
        float bb = bs[o];
        float4 v;
        v.x = fmaxf(fmaf(w0, x0.x, fmaf(w1, x1.x, fmaf(w2, x2.x, fmaf(w3, e0, bb)))), 0.0f);
        v.y = fmaxf(fmaf(w0, x0.y, fmaf(w1, x1.y, fmaf(w2, x2.y, fmaf(w3, e1, bb)))), 0.0f);
        v.z = fmaxf(fmaf(w0, x0.z, fmaf(w1, x1.z, fmaf(w2, x2.z, fmaf(w3, e2, bb)))), 0.0f);
        v.w = fmaxf(fmaf(w0, x0.w, fmaf(w1, x1.w, fmaf(w2, x2.w, fmaf(w3, e3, bb)))), 0.0f);
        *(float4*)(ob + (size_t)o * PLANE) = v;
    }
}

// ---------------------------------------------------------------------------
extern "C" void kernel_launch(void* const* d_in, const int* in_sizes, int n_in,
                              void* d_out, int out_size) {
    (void)in_sizes; (void)n_in; (void)out_size;
    const float* x  = (const float*)d_in[0];
    const float* Wm = (const float*)d_in[1];
    const float* b  = (const float*)d_in[2];
    float* out = (float*)d_out;

    dim3 b1(32, 16), g1(IMG_W / 32, IMG_H / 64, N_IMG);
    canny_nms_kernel<<<g1, b1>>>(x);

    hysteresis_kernel<<<N_IMG, 1024>>>();

    int total_threads = N_IMG * PLANE / 4;
    output_kernel<<<total_threads / 256, 256>>>(x, Wm, b, out);
}

// round 3
// speedup vs baseline: 1.1088x; 1.0175x over previous
#include <cuda_runtime.h>
#include <cstdint>

#define IMG_H 512
#define IMG_W 512
#define N_IMG 16
#define WORDS_PER_ROW 16
#define WORDS_PER_IMG (IMG_H * WORDS_PER_ROW)   // 8192
#define PLANE (IMG_H * IMG_W)

__device__ unsigned g_strong[N_IMG * WORDS_PER_IMG];
__device__ unsigned g_weak  [N_IMG * WORDS_PER_IMG];
__device__ unsigned g_edge  [N_IMG * WORDS_PER_IMG];

// ---------------------------------------------------------------------------
// K1: gray -> sobel -> NMS -> strong/weak bitmasks.
// Tile 32 wide x 64 tall, blockDim (32,8): thread = (column, 8-row strip).
// Mags live in registers; neighbor columns via warp shuffle. No mag smem.
// ---------------------------------------------------------------------------
__global__ __launch_bounds__(256, 3) void canny_nms_kernel(const float* __restrict__ x) {
    const int img = blockIdx.z;
    const int tx0 = blockIdx.x * 32;
    const int ty0 = blockIdx.y * 64;

    __shared__ float gs[68][37];   // gray: rows ty0-2..ty0+65, cols tx0-2..tx0+33

    const int tx = threadIdx.x, ty = threadIdx.y;
    const int tid = ty * 32 + tx;
    const float* xb = x + (size_t)img * 3 * PLANE;

    // Phase 1: gray 68x36 (edge-clamped)
    for (int i = tid; i < 68 * 36; i += 256) {
        int r = i / 36, c = i - r * 36;
        int gr = min(max(ty0 + r - 2, 0), IMG_H - 1);
        int gc = min(max(tx0 + c - 2, 0), IMG_W - 1);
        const float* p = xb + gr * IMG_W + gc;
        float g = __fadd_rn(__fadd_rn(__fmul_rn(0.2989f, __ldg(p)),
                                      __fmul_rn(0.587f, __ldg(p + PLANE))),
                            __fmul_rn(0.114f, __ldg(p + 2 * PLANE)));
        gs[r][c] = floorf(fminf(fmaxf(g, 0.0f), 255.0f));
    }
    __syncthreads();

    const int y0 = ty * 8;   // strip top (tile-local)

    // Phase 2: own-column mag for rows j=0..9 (global row ty0+y0-1+j).
    // Rolling 3x3 gray window; also classify center rows into bitmasks.
    float mag[10];
    unsigned hm = 0, vm = 0, sm = 0;
    {
        float c00 = gs[y0][tx + 1],     c01 = gs[y0][tx + 2],     c02 = gs[y0][tx + 3];
        float c10 = gs[y0 + 1][tx + 1], c11 = gs[y0 + 1][tx + 2], c12 = gs[y0 + 1][tx + 3];
#pragma unroll
        for (int j = 0; j < 10; j++) {
            float c20 = gs[y0 + j + 2][tx + 1];
            float c21 = gs[y0 + j + 2][tx + 2];
            float c22 = gs[y0 + j + 2][tx + 3];
            float gx = (c02 + 2.0f * c12 + c22) - (c00 + 2.0f * c10 + c20);
            float gy = (c20 + 2.0f * c21 + c22) - (c00 + 2.0f * c01 + c02);
            float ax = fabsf(gx), ay = fabsf(gy);
            int gm = ty0 + y0 - 1 + j;
            mag[j] = ((unsigned)gm < (unsigned)IMG_H) ? (ax + ay) : 0.0f;
            if (ay <= 0.4142135623730951f * ax) hm |= 1u << j;
            if (ay >  2.414213562373095f  * ax) vm |= 1u << j;
            if (gx * gy >= 0.0f)                sm |= 1u << j;
            c00 = c10; c01 = c11; c02 = c12;
            c10 = c20; c11 = c21; c12 = c22;
        }
    }

    // Halo columns: lane 0 computes col tx0-1, lane 31 computes col tx0+32.
    float magH[10];
    if (tx == 0 || tx == 31) {
        bool valid = (tx == 0) ? (blockIdx.x > 0) : (blockIdx.x < gridDim.x - 1);
        int cb = (tx == 0) ? 0 : 33;
        float c00 = gs[y0][cb],     c01 = gs[y0][cb + 1],     c02 = gs[y0][cb + 2];
        float c10 = gs[y0 + 1][cb], c11 = gs[y0 + 1][cb + 1], c12 = gs[y0 + 1][cb + 2];
#pragma unroll
        for (int j = 0; j < 10; j++) {
            float c20 = gs[y0 + j + 2][cb];
            float c21 = gs[y0 + j + 2][cb + 1];
            float c22 = gs[y0 + j + 2][cb + 2];
            float gx = (c02 + 2.0f * c12 + c22) - (c00 + 2.0f * c10 + c20);
            float gy = (c20 + 2.0f * c21 + c22) - (c00 + 2.0f * c01 + c02);
            int gm = ty0 + y0 - 1 + j;
            magH[j] = (valid && (unsigned)gm < (unsigned)IMG_H)
                    ? (fabsf(gx) + fabsf(gy)) : 0.0f;
            c00 = c10; c01 = c11; c02 = c12;
            c10 = c20; c11 = c21; c12 = c22;
        }
    } else {
#pragma unroll
        for (int j = 0; j < 10; j++) magH[j] = 0.0f;
    }

    // Neighbor-column mags via shuffle (halo lanes substitute their computed column)
    float magL[10], magR[10];
#pragma unroll
    for (int j = 0; j < 10; j++) {
        float l = __shfl_up_sync(0xffffffffu, mag[j], 1);
        float r = __shfl_down_sync(0xffffffffu, mag[j], 1);
        magL[j] = (tx == 0)  ? magH[j] : l;
        magR[j] = (tx == 31) ? magH[j] : r;
    }

    // Phase 3: NMS + ballot for the 8 center rows
#pragma unroll
    for (int k = 0; k < 8; k++) {
        int j = k + 1;
        float m = mag[j];
        bool horiz = (hm >> j) & 1u;
        bool vert  = (vm >> j) & 1u;
        bool ssg   = (sm >> j) & 1u;
        float n1 = horiz ? magR[j] : (vert ? mag[k]     : (ssg ? magL[k]     : magR[k]));
        float n2 = horiz ? magL[j] : (vert ? mag[k + 2] : (ssg ? magR[k + 2] : magL[k + 2]));
        bool keep = (m > n1) && (m >= n2);
        float nms = keep ? m : 0.0f;

        unsigned sb = __ballot_sync(0xffffffffu, nms > 150.0f);
        unsigned wb = __ballot_sync(0xffffffffu, nms > 50.0f);
        if (tx == 0) {
            int row = ty0 + y0 + k;
            int idx = (img * IMG_H + row) * WORDS_PER_ROW + blockIdx.x;
            g_strong[idx] = sb;
            g_weak[idx]   = wb;
        }
    }
}

// ---------------------------------------------------------------------------
// K2: hysteresis. Thread owns 8-row x 32-col strip in registers.
// Gauss-Seidel down+up passes + in-word weak-run closure (carry trick).
// ---------------------------------------------------------------------------
__device__ __forceinline__ unsigned Hd(unsigned m, unsigned l, unsigned r) {
    return m | (m << 1) | (m >> 1) | (l >> 31) | (r << 31);
}
__device__ __forceinline__ unsigned close_runs(unsigned g, unsigned w) {
    unsigned up = ((w + g) ^ w) & w;
    unsigned rg = __brev(g), rw = __brev(w);
    unsigned dn = __brev(((rw + rg) ^ rw) & rw);
    return g | up | dn;
}

__global__ __launch_bounds__(1024) void hysteresis_kernel() {
    const int img = blockIdx.x;
    __shared__ unsigned cur[WORDS_PER_IMG];   // 32 KB
    const unsigned* wp = g_weak   + img * WORDS_PER_IMG;
    const unsigned* sp = g_strong + img * WORDS_PER_IMG;
    const int tid = threadIdx.x;
    const int w  = tid & 15;
    const int r0 = (tid >> 4) << 3;

    unsigned reg[8], wk[8];
#pragma unroll
    for (int i = 0; i < 8; i++) {
        int idx = (r0 + i) * 16 + w;
        reg[i] = sp[idx];
        wk[i]  = wp[idx];
        cur[idx] = reg[i];
    }
    __syncthreads();

    for (;;) {
        unsigned lw[10], rw[10];
#pragma unroll
        for (int j = 0; j < 10; j++) {
            int r = r0 - 1 + j;
            bool ok = (r >= 0 && r < IMG_H);
            lw[j] = (ok && w > 0)  ? cur[r * 16 + w - 1] : 0u;
            rw[j] = (ok && w < 15) ? cur[r * 16 + w + 1] : 0u;
        }
        unsigned ab = (r0 > 0)         ? cur[(r0 - 1) * 16 + w] : 0u;
        unsigned bl = (r0 + 8 < IMG_H) ? cur[(r0 + 8) * 16 + w] : 0u;

        unsigned changed = 0;
#pragma unroll
        for (int i = 0; i < 8; i++) {
            unsigned up_row = (i == 0) ? ab : reg[i - 1];
            unsigned dn_row = (i == 7) ? bl : reg[i + 1];
            unsigned dil = Hd(up_row, lw[i], rw[i])
                         | Hd(reg[i], lw[i + 1], rw[i + 1])
                         | Hd(dn_row, lw[i + 2], rw[i + 2]);
            unsigned g = reg[i] | (wk[i] & dil);
            unsigned nv = g ? close_runs(g, wk[i]) : 0u;
            changed |= nv ^ reg[i];
            reg[i] = nv;
        }
#pragma unroll
        for (int i = 7; i >= 0; i--) {
            unsigned up_row = (i == 0) ? ab : reg[i - 1];
            unsigned dn_row = (i == 7) ? bl : reg[i + 1];
            unsigned dil = Hd(up_row, lw[i], rw[i])
                         | Hd(reg[i], lw[i + 1], rw[i + 1])
                         | Hd(dn_row, lw[i + 2], rw[i + 2]);
            unsigned g = reg[i] | (wk[i] & dil);
            unsigned nv = g ? close_runs(g, wk[i]) : 0u;
            changed |= nv ^ reg[i];
            reg[i] = nv;
        }

        __syncthreads();
#pragma unroll
        for (int i = 0; i < 8; i++) cur[(r0 + i) * 16 + w] = reg[i];
        if (!__syncthreads_or(changed != 0)) break;
    }

    unsigned* ep = g_edge + img * WORDS_PER_IMG;
#pragma unroll
    for (int i = 0; i < 8; i++) ep[(r0 + i) * 16 + w] = reg[i];
}

// ---------------------------------------------------------------------------
// K3: epilogue (537 MB write-bound). Streaming stores.
// ---------------------------------------------------------------------------
__global__ __launch_bounds__(256) void output_kernel(const float* __restrict__ x,
                                                     const float* __restrict__ Wm,
                                                     const float* __restrict__ bias,
                                                     float* __restrict__ out) {
    __shared__ float Ws[128];
    __shared__ float bs[32];
    const int tid = threadIdx.x;
    if (tid < 128) Ws[tid] = Wm[tid];
    if (tid < 32)  bs[tid] = bias[tid];
    __syncthreads();

    const long gt  = (long)blockIdx.x * blockDim.x + tid;
    const int img  = (int)(gt >> 16);
    const int pix  = ((int)gt & 65535) << 2;

    const float* xb = x + (size_t)img * 3 * PLANE;
    float4 x0 = __ldg((const float4*)(xb + pix));
    float4 x1 = __ldg((const float4*)(xb + PLANE + pix));
    float4 x2 = __ldg((const float4*)(xb + 2 * PLANE + pix));

    unsigned ew = g_edge[img * WORDS_PER_IMG + (pix >> 5)];
    int sh = pix & 31;
    float e0 = ((ew >> (sh    )) & 1u) ? 255.0f : 0.0f;
    float e1 = ((ew >> (sh + 1)) & 1u) ? 255.0f : 0.0f;
    float e2 = ((ew >> (sh + 2)) & 1u) ? 255.0f : 0.0f;
    float e3 = ((ew >> (sh + 3)) & 1u) ? 255.0f : 0.0f;

    float* ob = out + (size_t)img * 32 * PLANE + pix;
#pragma unroll 8
    for (int o = 0; o < 32; o++) {
        float w0 = Ws[4 * o], w1 = Ws[4 * o + 1], w2 = Ws[4 * o + 2], w3 = Ws[4 * o + 3];
        float bb = bs[o];
        float4 v;
        v.x = fmaxf(fmaf(w0, x0.x, fmaf(w1, x1.x, fmaf(w2, x2.x, fmaf(w3, e0, bb)))), 0.0f);
        v.y = fmaxf(fmaf(w0, x0.y, fmaf(w1, x1.y, fmaf(w2, x2.y, fmaf(w3, e1, bb)))), 0.0f);
        v.z = fmaxf(fmaf(w0, x0.z, fmaf(w1, x1.z, fmaf(w2, x2.z, fmaf(w3, e2, bb)))), 0.0f);
        v.w = fmaxf(fmaf(w0, x0.w, fmaf(w1, x1.w, fmaf(w2, x2.w, fmaf(w3, e3, bb)))), 0.0f);
        __stcs((float4*)(ob + (size_t)o * PLANE), v);
    }
}

// ---------------------------------------------------------------------------
extern "C" void kernel_launch(void* const* d_in, const int* in_sizes, int n_in,
                              void* d_out, int out_size) {
    (void)in_sizes; (void)n_in; (void)out_size;
    const float* x  = (const float*)d_in[0];
    const float* Wm = (const float*)d_in[1];
    const float* b  = (const float*)d_in[2];
    float* out = (float*)d_out;

    dim3 b1(32, 8), g1(IMG_W / 32, IMG_H / 64, N_IMG);
    canny_nms_kernel<<<g1, b1>>>(x);

    hysteresis_kernel<<<N_IMG, 1024>>>();

    int total_threads = N_IMG * PLANE / 4;
    output_kernel<<<total_threads / 256, 256>>>(x, Wm, b, out);
}

// round 4
// speedup vs baseline: 1.1453x; 1.0330x over previous
#include <cuda_runtime.h>
#include <cstdint>

#define IMG_H 512
#define IMG_W 512
#define N_IMG 16
#define WORDS_PER_ROW 16
#define WORDS_PER_IMG (IMG_H * WORDS_PER_ROW)   // 8192
#define PLANE (IMG_H * IMG_W)

__device__ unsigned g_strong[N_IMG * WORDS_PER_IMG];
__device__ unsigned g_weak  [N_IMG * WORDS_PER_IMG];
__device__ unsigned g_edge  [N_IMG * WORDS_PER_IMG];

// ---------------------------------------------------------------------------
// K1: gray -> sobel -> NMS -> strong/weak bitmasks.
// Tile 32 wide x 64 tall, blockDim (32,16): thread = (column, 4-row strip).
// Mags in registers; neighbor columns via warp shuffle. No mag smem.
// ---------------------------------------------------------------------------
__global__ __launch_bounds__(512, 3) void canny_nms_kernel(const float* __restrict__ x) {
    const int img = blockIdx.z;
    const int tx0 = blockIdx.x * 32;
    const int ty0 = blockIdx.y * 64;

    __shared__ float gs[68][37];   // gray: rows ty0-2..ty0+65, cols tx0-2..tx0+33

    const int tx = threadIdx.x, ty = threadIdx.y;
    const float* xb = x + (size_t)img * 3 * PLANE;

    // Phase 1: gray 68x36 (edge-clamped), structured loop (no div/mod)
    for (int r = ty; r < 68; r += 16) {
        int gr = min(max(ty0 + r - 2, 0), IMG_H - 1);
        const float* rb = xb + gr * IMG_W;
        {
            int gc = min(max(tx0 + tx - 2, 0), IMG_W - 1);
            float g = __fadd_rn(__fadd_rn(__fmul_rn(0.2989f, __ldg(rb + gc)),
                                          __fmul_rn(0.587f, __ldg(rb + PLANE + gc))),
                                __fmul_rn(0.114f, __ldg(rb + 2 * PLANE + gc)));
            gs[r][tx] = floorf(fminf(fmaxf(g, 0.0f), 255.0f));
        }
        if (tx < 4) {
            int c = 32 + tx;
            int gc = min(max(tx0 + c - 2, 0), IMG_W - 1);
            float g = __fadd_rn(__fadd_rn(__fmul_rn(0.2989f, __ldg(rb + gc)),
                                          __fmul_rn(0.587f, __ldg(rb + PLANE + gc))),
                                __fmul_rn(0.114f, __ldg(rb + 2 * PLANE + gc)));
            gs[r][c] = floorf(fminf(fmaxf(g, 0.0f), 255.0f));
        }
    }
    __syncthreads();

    const int y0 = ty * 4;   // strip top (tile-local)

    // Phase 2: own-column mag for rows j=0..5 (global row ty0+y0-1+j).
    float mag[6];
    unsigned cls = 0;   // bits j: horiz, bits 8+j: vert, bits 16+j: same-sign
    {
        float c00 = gs[y0][tx + 1],     c01 = gs[y0][tx + 2],     c02 = gs[y0][tx + 3];
        float c10 = gs[y0 + 1][tx + 1], c11 = gs[y0 + 1][tx + 2], c12 = gs[y0 + 1][tx + 3];
#pragma unroll
        for (int j = 0; j < 6; j++) {
            float c20 = gs[y0 + j + 2][tx + 1];
            float c21 = gs[y0 + j + 2][tx + 2];
            float c22 = gs[y0 + j + 2][tx + 3];
            float gx = (c02 + 2.0f * c12 + c22) - (c00 + 2.0f * c10 + c20);
            float gy = (c20 + 2.0f * c21 + c22) - (c00 + 2.0f * c01 + c02);
            float ax = fabsf(gx), ay = fabsf(gy);
            int gm = ty0 + y0 - 1 + j;
            mag[j] = ((unsigned)gm < (unsigned)IMG_H) ? (ax + ay) : 0.0f;
            if (ay <= 0.4142135623730951f * ax) cls |= 1u << j;
            if (ay >  2.414213562373095f  * ax) cls |= 1u << (8 + j);
            if (gx * gy >= 0.0f)                cls |= 1u << (16 + j);
            c00 = c10; c01 = c11; c02 = c12;
            c10 = c20; c11 = c21; c12 = c22;
        }
    }

    // Halo columns: lane 0 computes col tx0-1, lane 31 computes col tx0+32.
    float magH[6];
#pragma unroll
    for (int j = 0; j < 6; j++) magH[j] = 0.0f;
    if (tx == 0 || tx == 31) {
        bool valid = (tx == 0) ? (blockIdx.x > 0) : (blockIdx.x < gridDim.x - 1);
        if (valid) {
            int cb = (tx == 0) ? 0 : 33;
            float c00 = gs[y0][cb],     c01 = gs[y0][cb + 1],     c02 = gs[y0][cb + 2];
            float c10 = gs[y0 + 1][cb], c11 = gs[y0 + 1][cb + 1], c12 = gs[y0 + 1][cb + 2];
#pragma unroll
            for (int j = 0; j < 6; j++) {
                float c20 = gs[y0 + j + 2][cb];
                float c21 = gs[y0 + j + 2][cb + 1];
                float c22 = gs[y0 + j + 2][cb + 2];
                float gx = (c02 + 2.0f * c12 + c22) - (c00 + 2.0f * c10 + c20);
                float gy = (c20 + 2.0f * c21 + c22) - (c00 + 2.0f * c01 + c02);
                int gm = ty0 + y0 - 1 + j;
                if ((unsigned)gm < (unsigned)IMG_H) magH[j] = fabsf(gx) + fabsf(gy);
                c00 = c10; c01 = c11; c02 = c12;
                c10 = c20; c11 = c21; c12 = c22;
            }
        }
    }

    // Neighbor-column mags via shuffle (halo lanes substitute their column)
    float magL[6], magR[6];
#pragma unroll
    for (int j = 0; j < 6; j++) {
        float l = __shfl_up_sync(0xffffffffu, mag[j], 1);
        float r = __shfl_down_sync(0xffffffffu, mag[j], 1);
        magL[j] = (tx == 0)  ? magH[j] : l;
        magR[j] = (tx == 31) ? magH[j] : r;
    }

    // Phase 3: NMS + ballot for the 4 center rows
#pragma unroll
    for (int k = 0; k < 4; k++) {
        int j = k + 1;
        float m = mag[j];
        bool horiz = (cls >> j) & 1u;
        bool vert  = (cls >> (8 + j)) & 1u;
        bool ssg   = (cls >> (16 + j)) & 1u;
        float n1 = horiz ? magR[j] : (vert ? mag[k]     : (ssg ? magL[k]     : magR[k]));
        float n2 = horiz ? magL[j] : (vert ? mag[k + 2] : (ssg ? magR[k + 2] : magL[k + 2]));
        bool keep = (m > n1) && (m >= n2);
        float nms = keep ? m : 0.0f;

        unsigned sb = __ballot_sync(0xffffffffu, nms > 150.0f);
        unsigned wb = __ballot_sync(0xffffffffu, nms > 50.0f);
        if (tx == 0) {
            int row = ty0 + y0 + k;
            int idx = (img * IMG_H + row) * WORDS_PER_ROW + blockIdx.x;
            g_strong[idx] = sb;
            g_weak[idx]   = wb;
        }
    }
}

// ---------------------------------------------------------------------------
// K2: hysteresis. Thread owns 8-row x 32-col strip in registers.
// Gauss-Seidel down+up passes + in-word weak-run closure (carry trick).
// ---------------------------------------------------------------------------
__device__ __forceinline__ unsigned Hd(unsigned m, unsigned l, unsigned r) {
    return m | (m << 1) | (m >> 1) | (l >> 31) | (r << 31);
}
__device__ __forceinline__ unsigned close_runs(unsigned g, unsigned w) {
    unsigned up = ((w + g) ^ w) & w;
    unsigned rg = __brev(g), rw = __brev(w);
    unsigned dn = __brev(((rw + rg) ^ rw) & rw);
    return g | up | dn;
}

__global__ __launch_bounds__(1024) void hysteresis_kernel() {
    const int img = blockIdx.x;
    __shared__ unsigned cur[WORDS_PER_IMG];   // 32 KB
    const unsigned* wp = g_weak   + img * WORDS_PER_IMG;
    const unsigned* sp = g_strong + img * WORDS_PER_IMG;
    const int tid = threadIdx.x;
    const int w  = tid & 15;
    const int r0 = (tid >> 4) << 3;

    unsigned reg[8], wk[8];
#pragma unroll
    for (int i = 0; i < 8; i++) {
        int idx = (r0 + i) * 16 + w;
        reg[i] = sp[idx];
        wk[i]  = wp[idx];
        cur[idx] = reg[i];
    }
    __syncthreads();

    for (;;) {
        unsigned lw[10], rw[10];
#pragma unroll
        for (int j = 0; j < 10; j++) {
            int r = r0 - 1 + j;
            bool ok = (r >= 0 && r < IMG_H);
            lw[j] = (ok && w > 0)  ? cur[r * 16 + w - 1] : 0u;
            rw[j] = (ok && w < 15) ? cur[r * 16 + w + 1] : 0u;
        }
        unsigned ab = (r0 > 0)         ? cur[(r0 - 1) * 16 + w] : 0u;
        unsigned bl = (r0 + 8 < IMG_H) ? cur[(r0 + 8) * 16 + w] : 0u;

        unsigned changed = 0;
#pragma unroll
        for (int i = 0; i < 8; i++) {
            unsigned up_row = (i == 0) ? ab : reg[i - 1];
            unsigned dn_row = (i == 7) ? bl : reg[i + 1];
            unsigned dil = Hd(up_row, lw[i], rw[i])
                         | Hd(reg[i], lw[i + 1], rw[i + 1])
                         | Hd(dn_row, lw[i + 2], rw[i + 2]);
            unsigned g = reg[i] | (wk[i] & dil);
            unsigned nv = g ? close_runs(g, wk[i]) : 0u;
            changed |= nv ^ reg[i];
            reg[i] = nv;
        }
#pragma unroll
        for (int i = 7; i >= 0; i--) {
            unsigned up_row = (i == 0) ? ab : reg[i - 1];
            unsigned dn_row = (i == 7) ? bl : reg[i + 1];
            unsigned dil = Hd(up_row, lw[i], rw[i])
                         | Hd(reg[i], lw[i + 1], rw[i + 1])
                         | Hd(dn_row, lw[i + 2], rw[i + 2]);
            unsigned g = reg[i] | (wk[i] & dil);
            unsigned nv = g ? close_runs(g, wk[i]) : 0u;
            changed |= nv ^ reg[i];
            reg[i] = nv;
        }

        __syncthreads();
#pragma unroll
        for (int i = 0; i < 8; i++) cur[(r0 + i) * 16 + w] = reg[i];
        if (!__syncthreads_or(changed != 0)) break;
    }

    unsigned* ep = g_edge + img * WORDS_PER_IMG;
#pragma unroll
    for (int i = 0; i < 8; i++) ep[(r0 + i) * 16 + w] = reg[i];
}

// ---------------------------------------------------------------------------
// K3: epilogue (537 MB write-bound). Streaming stores.
// ---------------------------------------------------------------------------
__global__ __launch_bounds__(256) void output_kernel(const float* __restrict__ x,
                                                     const float* __restrict__ Wm,
                                                     const float* __restrict__ bias,
                                                     float* __restrict__ out) {
    __shared__ float Ws[128];
    __shared__ float bs[32];
    const int tid = threadIdx.x;
    if (tid < 128) Ws[tid] = Wm[tid];
    if (tid < 32)  bs[tid] = bias[tid];
    __syncthreads();

    const long gt  = (long)blockIdx.x * blockDim.x + tid;
    const int img  = (int)(gt >> 16);
    const int pix  = ((int)gt & 65535) << 2;

    const float* xb = x + (size_t)img * 3 * PLANE;
    float4 x0 = __ldg((const float4*)(xb + pix));
    float4 x1 = __ldg((const float4*)(xb + PLANE + pix));
    float4 x2 = __ldg((const float4*)(xb + 2 * PLANE + pix));

    unsigned ew = g_edge[img * WORDS_PER_IMG + (pix >> 5)];
    int sh = pix & 31;
    float e0 = ((ew >> (sh    )) & 1u) ? 255.0f : 0.0f;
    float e1 = ((ew >> (sh + 1)) & 1u) ? 255.0f : 0.0f;
    float e2 = ((ew >> (sh + 2)) & 1u) ? 255.0f : 0.0f;
    float e3 = ((ew >> (sh + 3)) & 1u) ? 255.0f : 0.0f;

    float* ob = out + (size_t)img * 32 * PLANE + pix;
#pragma unroll 8
    for (int o = 0; o < 32; o++) {
        float w0 = Ws[4 * o], w1 = Ws[4 * o + 1], w2 = Ws[4 * o + 2], w3 = Ws[4 * o + 3];
        float bb = bs[o];
        float4 v;
        v.x = fmaxf(fmaf(w0, x0.x, fmaf(w1, x1.x, fmaf(w2, x2.x, fmaf(w3, e0, bb)))), 0.0f);
        v.y = fmaxf(fmaf(w0, x0.y, fmaf(w1, x1.y, fmaf(w2, x2.y, fmaf(w3, e1, bb)))), 0.0f);
        v.z = fmaxf(fmaf(w0, x0.z, fmaf(w1, x1.z, fmaf(w2, x2.z, fmaf(w3, e2, bb)))), 0.0f);
        v.w = fmaxf(fmaf(w0, x0.w, fmaf(w1, x1.w, fmaf(w2, x2.w, fmaf(w3, e3, bb)))), 0.0f);
        __stcs((float4*)(ob + (size_t)o * PLANE), v);
    }
}

// ---------------------------------------------------------------------------
extern "C" void kernel_launch(void* const* d_in, const int* in_sizes, int n_in,
                              void* d_out, int out_size) {
    (void)in_sizes; (void)n_in; (void)out_size;
    const float* x  = (const float*)d_in[0];
    const float* Wm = (const float*)d_in[1];
    const float* b  = (const float*)d_in[2];
    float* out = (float*)d_out;

    dim3 b1(32, 16), g1(IMG_W / 32, IMG_H / 64, N_IMG);
    canny_nms_kernel<<<g1, b1>>>(x);

    hysteresis_kernel<<<N_IMG, 1024>>>();

    int total_threads = N_IMG * PLANE / 4;
    output_kernel<<<total_threads / 256, 256>>>(x, Wm, b, out);
}